// round 3
// baseline (speedup 1.0000x reference)
#include <cuda_runtime.h>

// ============================================================================
// Fused scaled-dot-product attention (fp32), B=2 H=16 S=2048 D=64.
// Outputs: d_out[0 : B*H*S*D)          = context
//          d_out[B*H*S*D : +B*H*S*S)   = attention (post-softmax)
//
// One block (512 threads, 16 warps) = one (b*h, 16-query-row) tile.
// 16 warps/SM (4 per SMSP) to hide LDS/issue latency that capped the
// 256-thread version at issue=27%.
// ============================================================================

namespace {

constexpr int Bc  = 2;
constexpr int Hc  = 16;
constexpr int Sc  = 2048;
constexpr int Dc  = 64;
constexpr int TQ  = 16;    // query rows per block
constexpr int KTW = 256;   // K-tile width (score columns per supertile)
constexpr int KP  = 65;    // K smem pitch (odd -> conflict-free column reads)
constexpr int SP  = 2052;  // score row pitch
constexpr int NT  = 512;   // threads per block (16 warps)

constexpr int SM_QT     = 0;                   // Qt[d][q]  : 64*16 = 1024
constexpr int SM_INV    = SM_QT + Dc * TQ;     // inv[16]
constexpr int SM_SC     = SM_INV + 16;         // SC[q][SP] : 16*2052
constexpr int SM_KV     = SM_SC + TQ * SP;     // KV: K tile 256*65 / V tile / partials
constexpr int SM_FLOATS = SM_KV + KTW * KP;    // 50512 floats = 202048 bytes

__device__ __forceinline__ unsigned long long pk2(float x, float y) {
    unsigned long long r;
    asm("mov.b64 %0, {%1, %2};"
        : "=l"(r) : "r"(__float_as_uint(x)), "r"(__float_as_uint(y)));
    return r;
}

__device__ __forceinline__ void upk2(unsigned long long v, float& x, float& y) {
    unsigned int a, b;
    asm("mov.b64 {%0, %1}, %2;" : "=r"(a), "=r"(b) : "l"(v));
    x = __uint_as_float(a);
    y = __uint_as_float(b);
}

__device__ __forceinline__ unsigned long long
fma2(unsigned long long a, unsigned long long b, unsigned long long c) {
    unsigned long long d;
    asm("fma.rn.f32x2 %0, %1, %2, %3;" : "=l"(d) : "l"(a), "l"(b), "l"(c));
    return d;
}

} // namespace

__global__ void __launch_bounds__(NT, 1)
attn_fused_kernel(const float* __restrict__ Q, const float* __restrict__ K,
                  const float* __restrict__ V, const float* __restrict__ M,
                  float* __restrict__ OC, float* __restrict__ OA)
{
    extern __shared__ float sm[];
    float* Qt    = sm + SM_QT;
    float* sminv = sm + SM_INV;
    float* SC    = sm + SM_SC;
    float* KV    = sm + SM_KV;

    const int t  = threadIdx.x;
    const int qt = blockIdx.x;   // query tile (0..127)
    const int bh = blockIdx.y;   // b*H + h    (0..31)

    const float* Qb = Q + ((long)bh * Sc + qt * TQ) * Dc;
    const float* Kb = K + (long)bh * Sc * Dc;
    const float* Vb = V + (long)bh * Sc * Dc;
    const float* Mb = M + ((long)bh * Sc + (long)qt * TQ) * Sc;
    float*       Ab = OA + ((long)bh * Sc + (long)qt * TQ) * Sc;
    float*       Cb = OC + ((long)bh * Sc + qt * TQ) * Dc;

    // ---------------- Phase 0: stage Q transposed (Qt[d][q]) ----------------
    if (t < 256) {
        const int q  = t >> 4;          // 0..15
        const int d0 = (t & 15) << 2;   // 0,4,...,60
        float4 v = *reinterpret_cast<const float4*>(Qb + q * Dc + d0);
        Qt[(d0 + 0) * TQ + q] = v.x;
        Qt[(d0 + 1) * TQ + q] = v.y;
        Qt[(d0 + 2) * TQ + q] = v.z;
        Qt[(d0 + 3) * TQ + q] = v.w;
    }

    const int a = t >> 8;    // q octet: rows 8a..8a+7
    const int g = t & 255;   // k column within supertile

    // ---------------- Phase 1: S = (Q K^T) * 1/sqrt(D) ----------------------
    const float scl = 0.125f;  // 1/sqrt(64)
    for (int st = 0; st < Sc / KTW; ++st) {
        __syncthreads();
        // Load K supertile rows [st*256, +256) into KV[k][KP], coalesced LDG.
        {
            const float* src = Kb + (long)st * KTW * Dc;
            #pragma unroll
            for (int ii = 0; ii < (KTW * Dc) / (NT * 4); ++ii) {  // 8 iters
                const int idx4 = t + NT * ii;
                const int kr = idx4 >> 4;
                const int d0 = (idx4 & 15) << 2;
                float4 v = *reinterpret_cast<const float4*>(src + (size_t)idx4 * 4);
                float* dst = KV + kr * KP + d0;
                dst[0] = v.x; dst[1] = v.y; dst[2] = v.z; dst[3] = v.w;
            }
        }
        __syncthreads();

        // acc[j]: q-pair j (rows 8a+2j, 8a+2j+1) for this thread's column g.
        unsigned long long a0 = 0ull, a1 = 0ull, a2 = 0ull, a3 = 0ull;
        const float* kcol = KV + g * KP;
        #pragma unroll 8
        for (int d = 0; d < Dc; ++d) {
            const ulonglong2 qA =
                *reinterpret_cast<const ulonglong2*>(Qt + d * TQ + 8 * a);
            const ulonglong2 qB =
                *reinterpret_cast<const ulonglong2*>(Qt + d * TQ + 8 * a + 4);
            const float k = kcol[d];
            const unsigned long long kk = pk2(k, k);
            a0 = fma2(qA.x, kk, a0);
            a1 = fma2(qA.y, kk, a1);
            a2 = fma2(qB.x, kk, a2);
            a3 = fma2(qB.y, kk, a3);
        }

        {
            float s0, s1;
            float* col = SC + st * KTW + g;
            upk2(a0, s0, s1);
            col[(8*a + 0) * SP] = s0 * scl;  col[(8*a + 1) * SP] = s1 * scl;
            upk2(a1, s0, s1);
            col[(8*a + 2) * SP] = s0 * scl;  col[(8*a + 3) * SP] = s1 * scl;
            upk2(a2, s0, s1);
            col[(8*a + 4) * SP] = s0 * scl;  col[(8*a + 5) * SP] = s1 * scl;
            upk2(a3, s0, s1);
            col[(8*a + 6) * SP] = s0 * scl;  col[(8*a + 7) * SP] = s1 * scl;
        }
    }
    __syncthreads();

    // ------- Softmax (+mask): leave UNNORMALIZED exp in SC; write attention -
    {
        const int r = t >> 5, lane = t & 31;    // 16 warps -> 16 rows
        float* row = SC + r * SP;
        const float* mrow = Mb + (long)r * Sc;

        float mx = -3.0e38f;
        #pragma unroll
        for (int i = 0; i < Sc / 128; ++i) {  // 16 iters of float4
            const int c = (lane + i * 32) << 2;
            float4 s = *reinterpret_cast<float4*>(row + c);
            const float4 m = *reinterpret_cast<const float4*>(mrow + c);
            s.x += m.x; s.y += m.y; s.z += m.z; s.w += m.w;
            *reinterpret_cast<float4*>(row + c) = s;
            mx = fmaxf(mx, fmaxf(fmaxf(s.x, s.y), fmaxf(s.z, s.w)));
        }
        #pragma unroll
        for (int o = 16; o > 0; o >>= 1)
            mx = fmaxf(mx, __shfl_xor_sync(0xffffffffu, mx, o));

        float sum = 0.f;
        #pragma unroll
        for (int i = 0; i < Sc / 128; ++i) {
            const int c = (lane + i * 32) << 2;
            float4 s = *reinterpret_cast<float4*>(row + c);
            s.x = __expf(s.x - mx); s.y = __expf(s.y - mx);
            s.z = __expf(s.z - mx); s.w = __expf(s.w - mx);
            *reinterpret_cast<float4*>(row + c) = s;   // unnormalized exp
            sum += (s.x + s.y) + (s.z + s.w);
        }
        #pragma unroll
        for (int o = 16; o > 0; o >>= 1)
            sum += __shfl_xor_sync(0xffffffffu, sum, o);
        const float inv = 1.0f / sum;
        if (lane == 0) sminv[r] = inv;

        float* arow = Ab + (long)r * Sc;
        #pragma unroll
        for (int i = 0; i < Sc / 128; ++i) {
            const int c = (lane + i * 32) << 2;
            float4 s = *reinterpret_cast<float4*>(row + c);
            s.x *= inv; s.y *= inv; s.z *= inv; s.w *= inv;
            *reinterpret_cast<float4*>(arow + c) = s;  // attention out only
        }
    }

    // ---------------- Phase 2: C = P @ V (P = unnormalized exp) -------------
    const int p  = t >> 5;         // warp id: k rows p*8..p*8+7 per V tile
    const int a2 = (t >> 4) & 1;   // q octet: rows 8*a2..8*a2+7
    const int dg = t & 15;         // d quad : cols 4*dg..4*dg+3

    unsigned long long cA[8], cB[8];   // per q-row r: (d0,d1) and (d2,d3)
    #pragma unroll
    for (int r = 0; r < 8; ++r) { cA[r] = 0ull; cB[r] = 0ull; }

    for (int vt = 0; vt < Sc / 128; ++vt) {   // 16 V tiles of 128 rows
        __syncthreads();
        {
            const float4* src =
                reinterpret_cast<const float4*>(Vb + (long)vt * 128 * Dc);
            float4* dst = reinterpret_cast<float4*>(KV);
            #pragma unroll
            for (int ii = 0; ii < (128 * Dc) / (NT * 4); ++ii)  // 4 iters
                dst[t + NT * ii] = src[t + NT * ii];
        }
        __syncthreads();

        const float* pcb = SC + vt * 128 + p * 8;
        #pragma unroll
        for (int kk = 0; kk < 8; kk += 2) {
            const float* vrow = KV + (p * 8 + kk) * Dc + 4 * dg;
            const ulonglong2 v0 = *reinterpret_cast<const ulonglong2*>(vrow);
            const ulonglong2 v1 = *reinterpret_cast<const ulonglong2*>(vrow + Dc);
            #pragma unroll
            for (int r = 0; r < 8; ++r) {
                const float2 pv =
                    *reinterpret_cast<const float2*>(pcb + (8*a2 + r) * SP + kk);
                const unsigned long long pa = pk2(pv.x, pv.x);
                const unsigned long long pb = pk2(pv.y, pv.y);
                cA[r] = fma2(pa, v0.x, cA[r]);
                cB[r] = fma2(pa, v0.y, cB[r]);
                cA[r] = fma2(pb, v1.x, cA[r]);
                cB[r] = fma2(pb, v1.y, cB[r]);
            }
        }
    }

    // Scale partials by 1/sum, store per-warp partials, reduce over 16 slices.
    __syncthreads();
    #pragma unroll
    for (int r = 0; r < 8; ++r) {
        const int row = 8 * a2 + r;
        const float inv = sminv[row];
        float s0, s1, s2, s3;
        upk2(cA[r], s0, s1);
        upk2(cB[r], s2, s3);
        *reinterpret_cast<float4*>(KV + p * 1024 + row * Dc + 4 * dg) =
            make_float4(s0 * inv, s1 * inv, s2 * inv, s3 * inv);
    }
    __syncthreads();
    {
        // 1024 context floats = 512 float2 slots; one per thread.
        const float2* kv2 = reinterpret_cast<const float2*>(KV);
        float2 o = make_float2(0.f, 0.f);
        #pragma unroll
        for (int pp = 0; pp < 16; ++pp) {
            const float2 r = kv2[pp * 512 + t];
            o.x += r.x; o.y += r.y;
        }
        reinterpret_cast<float2*>(Cb)[t] = o;
    }
}

extern "C" void kernel_launch(void* const* d_in, const int* in_sizes, int n_in,
                              void* d_out, int out_size) {
    const float* Q = (const float*)d_in[0];
    const float* K = (const float*)d_in[1];
    const float* V = (const float*)d_in[2];
    const float* M = (const float*)d_in[3];

    float* ctx  = (float*)d_out;
    float* attn = (float*)d_out + (size_t)Bc * Hc * Sc * Dc;  // context, then attention

    const size_t smem_bytes = (size_t)SM_FLOATS * sizeof(float);
    cudaFuncSetAttribute(attn_fused_kernel,
                         cudaFuncAttributeMaxDynamicSharedMemorySize,
                         (int)smem_bytes);

    dim3 grid(Sc / TQ, Bc * Hc);   // (128, 32)
    attn_fused_kernel<<<grid, NT, smem_bytes>>>(Q, K, V, M, ctx, attn);
}